// round 9
// baseline (speedup 1.0000x reference)
#include <cuda_runtime.h>
#include <math.h>
#include <math_constants.h>

#define D_DIM 128
#define MAXN  50048
#define EPS_F 1e-8f
#define FULL  0xffffffffu
#define GAP_THRESH 0.05f

typedef unsigned int u32;

__device__ float g_xp[(size_t)MAXN * D_DIM];

// ---------------------------------------------------------------------------
// tf32 helpers
// ---------------------------------------------------------------------------
__device__ __forceinline__ u32 to_tf32(float x) {
    u32 r; asm("cvt.rna.tf32.f32 %0, %1;" : "=r"(r) : "f"(x)); return r;
}
__device__ __forceinline__ void split_tf32(float x, u32& hi, u32& lo) {
    hi = to_tf32(x);
    float rem = x - __uint_as_float(hi);
    lo = to_tf32(rem);
}
__device__ __forceinline__ void mma_tf32(float* c, const u32* a, const u32* b) {
    asm volatile(
        "mma.sync.aligned.m16n8k8.row.col.f32.tf32.tf32.f32 "
        "{%0,%1,%2,%3}, {%4,%5,%6,%7}, {%8,%9}, {%0,%1,%2,%3};"
        : "+f"(c[0]), "+f"(c[1]), "+f"(c[2]), "+f"(c[3])
        : "r"(a[0]), "r"(a[1]), "r"(a[2]), "r"(a[3]), "r"(b[0]), "r"(b[1]));
}

#define KC    32
#define PITCH 36
#define BUF_FLOATS (128 * PITCH)

// ---------------------------------------------------------------------------
// Projection: Y = (X @ W^T) * sqrt(softplus(logd)+eps), 4-pass split-TF32.
// Fast approximate path (~1e-6 abs y error); knife-edge nodes are repaired
// exactly in the edge kernel.
// ---------------------------------------------------------------------------
__global__ __launch_bounds__(512, 1) void proj_mma_kernel(
    const float* __restrict__ X, const float* __restrict__ W,
    const float* __restrict__ logd, int N)
{
    extern __shared__ float smem[];
    float* scale = smem;
    float* Xhi = smem + 128;
    float* Xlo = Xhi + BUF_FLOATS;
    float* Whi = Xlo + BUF_FLOATS;
    float* Wlo = Whi + BUF_FLOATS;

    const int tid  = threadIdx.x;
    const int lane = tid & 31;
    const int wid  = tid >> 5;
    const int wm   = wid & 3;
    const int wn   = wid >> 2;
    const int m0   = blockIdx.x * 128;

    if (tid < 128) {
        float ld = logd[tid];
        float sp = (ld > 20.f) ? ld : log1pf(expf(ld));
        scale[tid] = sqrtf(sp + EPS_F);
    }

    float acc[2][4][4];
#pragma unroll
    for (int mt = 0; mt < 2; mt++)
#pragma unroll
        for (int nt = 0; nt < 4; nt++)
#pragma unroll
            for (int q = 0; q < 4; q++) acc[mt][nt][q] = 0.f;

    const int fr = lane >> 2;
    const int fc = lane & 3;

    for (int kt = 0; kt < 4; kt++) {
        __syncthreads();
#pragma unroll
        for (int it = 0; it < 2; it++) {
            int idx = tid + it * 512;
            int r   = idx >> 3;
            int k4  = (idx & 7) * 4;
            int gr = m0 + r;
            float4 xv = make_float4(0.f, 0.f, 0.f, 0.f);
            if (gr < N) xv = *(const float4*)(X + (size_t)gr * D_DIM + kt * KC + k4);
            u32 h0, l0, h1, l1, h2, l2, h3, l3;
            split_tf32(xv.x, h0, l0); split_tf32(xv.y, h1, l1);
            split_tf32(xv.z, h2, l2); split_tf32(xv.w, h3, l3);
            u32* xh = (u32*)(Xhi + r * PITCH + k4);
            u32* xl = (u32*)(Xlo + r * PITCH + k4);
            xh[0] = h0; xh[1] = h1; xh[2] = h2; xh[3] = h3;
            xl[0] = l0; xl[1] = l1; xl[2] = l2; xl[3] = l3;
            float4 wv = *(const float4*)(W + (size_t)r * D_DIM + kt * KC + k4);
            split_tf32(wv.x, h0, l0); split_tf32(wv.y, h1, l1);
            split_tf32(wv.z, h2, l2); split_tf32(wv.w, h3, l3);
            u32* wh = (u32*)(Whi + r * PITCH + k4);
            u32* wl = (u32*)(Wlo + r * PITCH + k4);
            wh[0] = h0; wh[1] = h1; wh[2] = h2; wh[3] = h3;
            wl[0] = l0; wl[1] = l1; wl[2] = l2; wl[3] = l3;
        }
        __syncthreads();

#pragma unroll
        for (int ks = 0; ks < KC / 8; ks++) {
            u32 ah[2][4], al[2][4];
#pragma unroll
            for (int mt = 0; mt < 2; mt++) {
                int rb = (wm * 32 + mt * 16 + fr) * PITCH + ks * 8 + fc;
                ah[mt][0] = *(u32*)(Xhi + rb);
                ah[mt][1] = *(u32*)(Xhi + rb + 8 * PITCH);
                ah[mt][2] = *(u32*)(Xhi + rb + 4);
                ah[mt][3] = *(u32*)(Xhi + rb + 8 * PITCH + 4);
                al[mt][0] = *(u32*)(Xlo + rb);
                al[mt][1] = *(u32*)(Xlo + rb + 8 * PITCH);
                al[mt][2] = *(u32*)(Xlo + rb + 4);
                al[mt][3] = *(u32*)(Xlo + rb + 8 * PITCH + 4);
            }
            u32 bh[4][2], bl[4][2];
#pragma unroll
            for (int nt = 0; nt < 4; nt++) {
                int nb = (wn * 32 + nt * 8 + fr) * PITCH + ks * 8 + fc;
                bh[nt][0] = *(u32*)(Whi + nb);
                bh[nt][1] = *(u32*)(Whi + nb + 4);
                bl[nt][0] = *(u32*)(Wlo + nb);
                bl[nt][1] = *(u32*)(Wlo + nb + 4);
            }
#pragma unroll
            for (int mt = 0; mt < 2; mt++)
#pragma unroll
                for (int nt = 0; nt < 4; nt++) {
                    mma_tf32(acc[mt][nt], ah[mt], bh[nt]);
                    mma_tf32(acc[mt][nt], ah[mt], bl[nt]);
                    mma_tf32(acc[mt][nt], al[mt], bh[nt]);
                    mma_tf32(acc[mt][nt], al[mt], bl[nt]);
                }
        }
    }

#pragma unroll
    for (int mt = 0; mt < 2; mt++) {
        int row0 = m0 + wm * 32 + mt * 16 + fr;
#pragma unroll
        for (int nt = 0; nt < 4; nt++) {
            int col = wn * 32 + nt * 8 + 2 * fc;
            float s0 = scale[col], s1 = scale[col + 1];
            if (row0 < N) {
                float2 o0 = make_float2(acc[mt][nt][0] * s0, acc[mt][nt][1] * s1);
                *(float2*)(g_xp + (size_t)row0 * D_DIM + col) = o0;
            }
            if (row0 + 8 < N) {
                float2 o1 = make_float2(acc[mt][nt][2] * s0, acc[mt][nt][3] * s1);
                *(float2*)(g_xp + (size_t)(row0 + 8) * D_DIM + col) = o1;
            }
        }
    }
}

// ---------------------------------------------------------------------------
// Exact y-row recompute: bitwise-identical to the fp32-sequential proj
// realization (fmaf ascending k 0..127, then * sqrt(softplus(logd)+eps)).
// Lane holds dims [4*lane, 4*lane+4).
// ---------------------------------------------------------------------------
__device__ __noinline__ float4 exact_row(
    const float* __restrict__ X, const float* __restrict__ W,
    const float* __restrict__ logd, int r, int lane)
{
    const float* xr = X + (size_t)r * D_DIM;
    const float* w0 = W + (size_t)(4 * lane + 0) * D_DIM;
    const float* w1 = W + (size_t)(4 * lane + 1) * D_DIM;
    const float* w2 = W + (size_t)(4 * lane + 2) * D_DIM;
    const float* w3 = W + (size_t)(4 * lane + 3) * D_DIM;
    float a0 = 0.f, a1 = 0.f, a2 = 0.f, a3 = 0.f;
    for (int k = 0; k < D_DIM; k++) {
        float xv = xr[k];
        a0 = fmaf(xv, w0[k], a0);
        a1 = fmaf(xv, w1[k], a1);
        a2 = fmaf(xv, w2[k], a2);
        a3 = fmaf(xv, w3[k], a3);
    }
    float4 y;
    {
        float ld = logd[4 * lane + 0];
        float sp = (ld > 20.f) ? ld : log1pf(expf(ld));
        y.x = a0 * sqrtf(sp + EPS_F);
    }
    {
        float ld = logd[4 * lane + 1];
        float sp = (ld > 20.f) ? ld : log1pf(expf(ld));
        y.y = a1 * sqrtf(sp + EPS_F);
    }
    {
        float ld = logd[4 * lane + 2];
        float sp = (ld > 20.f) ? ld : log1pf(expf(ld));
        y.z = a2 * sqrtf(sp + EPS_F);
    }
    {
        float ld = logd[4 * lane + 3];
        float sp = (ld > 20.f) ? ld : log1pf(expf(ld));
        y.w = a3 * sqrtf(sp + EPS_F);
    }
    return y;
}

// Butterfly transpose-reduce: p[16] per-lane partials -> per-lane raw score
// (lane l ends holding the full sum for neighbor rev4(l&15), then
// redistributed so lane n holds neighbor n's sum).
__device__ __forceinline__ float butterfly_score(float* p, int lane) {
    const bool b0 = lane & 1;
#pragma unroll
    for (int k = 0; k < 8; k++) {
        float send = b0 ? p[k] : p[k + 8];
        float recv = __shfl_xor_sync(FULL, send, 1);
        p[k] = (b0 ? p[k + 8] : p[k]) + recv;
    }
    const bool b1 = lane & 2;
#pragma unroll
    for (int k = 0; k < 4; k++) {
        float send = b1 ? p[k] : p[k + 4];
        float recv = __shfl_xor_sync(FULL, send, 2);
        p[k] = (b1 ? p[k + 4] : p[k]) + recv;
    }
    const bool b2 = lane & 4;
#pragma unroll
    for (int k = 0; k < 2; k++) {
        float send = b2 ? p[k] : p[k + 2];
        float recv = __shfl_xor_sync(FULL, send, 4);
        p[k] = (b2 ? p[k + 2] : p[k]) + recv;
    }
    const bool b3 = lane & 8;
    {
        float send = b3 ? p[0] : p[1];
        float recv = __shfl_xor_sync(FULL, send, 8);
        p[0] = (b3 ? p[1] : p[0]) + recv;
    }
    p[0] += __shfl_xor_sync(FULL, p[0], 16);
    const int l4  = lane & 15;
    const int rev = ((l4 & 1) << 3) | ((l4 & 2) << 1) | ((l4 & 4) >> 1) | ((l4 & 8) >> 3);
    return __shfl_sync(FULL, p[0], rev);
}

__device__ __forceinline__ void diff_sq(const float4& yi, const float4& v, float& out) {
    float dx = yi.x - v.x, dy = yi.y - v.y;
    float dz = yi.z - v.z, dw = yi.w - v.w;
    out = dx * dx + dy * dy + dz * dz + dw * dw;
}

// ---------------------------------------------------------------------------
// Edge kernel: scores from MMA-y; nodes whose top-k margin is small get an
// exact fp32-sequential recompute (matches reference realization).
// ---------------------------------------------------------------------------
__global__ __launch_bounds__(256, 5) void edge_kernel(
    const int* __restrict__ eidx, const float* __restrict__ logt,
    const float* __restrict__ X, const float* __restrict__ W,
    const float* __restrict__ logd,
    float* __restrict__ out, int N, int deg, int topk)
{
    const int warp = blockIdx.x * (blockDim.x >> 5) + (threadIdx.x >> 5);
    const int lane = threadIdx.x & 31;
    if (warp >= N) return;
    const int i = warp;

    const int* colp = eidx + (size_t)N * deg + (size_t)i * deg;
    int mycol = (lane < 16) ? colp[lane] : 0;

    const float rtemp = expf(-logt[0]);

    float s;
    {
        float4 yi = *(const float4*)(g_xp + (size_t)i * D_DIM + lane * 4);
        float p[16];
#pragma unroll
        for (int g = 0; g < 4; g++) {
            float4 v[4];
#pragma unroll
            for (int n = 0; n < 4; n++) {
                int c = __shfl_sync(FULL, mycol, g * 4 + n);
                v[n] = *(const float4*)(g_xp + (size_t)c * D_DIM + lane * 4);
            }
#pragma unroll
            for (int n = 0; n < 4; n++) diff_sq(yi, v[n], p[g * 4 + n]);
        }
        float raw = butterfly_score(p, lane);
        s = (lane < 16) ? (-raw * rtemp) : -CUDART_INF_F;
    }

    // stable rank (lax.top_k semantics: ties -> lower index)
    int rank = 0;
#pragma unroll
    for (int m = 0; m < 16; m++) {
        float sm = __shfl_sync(FULL, s, m);
        rank += (sm > s || (sm == s && m < lane)) ? 1 : 0;
    }
    bool sel = rank < topk;

    // selection margin: min(selected) - max(unselected)
    {
        float m1 = sel ? s : CUDART_INF_F;
        float m2 = (!sel && lane < 16) ? s : -CUDART_INF_F;
#pragma unroll
        for (int o = 16; o > 0; o >>= 1) {
            m1 = fminf(m1, __shfl_xor_sync(FULL, m1, o));
            m2 = fmaxf(m2, __shfl_xor_sync(FULL, m2, o));
        }
        if (m1 - m2 < GAP_THRESH) {
            // exact recompute: fp32-sequential y for self + all 16 neighbors
            float4 yi = exact_row(X, W, logd, i, lane);
            float p[16];
#pragma unroll 1
            for (int n = 0; n < 16; n++) {
                int c = __shfl_sync(FULL, mycol, n);
                float4 v = exact_row(X, W, logd, c, lane);
                diff_sq(yi, v, p[n]);
            }
            float raw = butterfly_score(p, lane);
            s = (lane < 16) ? (-raw * rtemp) : -CUDART_INF_F;
            rank = 0;
#pragma unroll
            for (int m = 0; m < 16; m++) {
                float sm = __shfl_sync(FULL, s, m);
                rank += (sm > s || (sm == s && m < lane)) ? 1 : 0;
            }
            sel = rank < topk;
        }
    }

    unsigned bal = __ballot_sync(FULL, sel);

    float smax = sel ? s : -CUDART_INF_F;
#pragma unroll
    for (int o = 8; o > 0; o >>= 1)
        smax = fmaxf(smax, __shfl_xor_sync(FULL, smax, o));
    float e = sel ? expf(s - smax) : 0.f;
    float esum = e;
#pragma unroll
    for (int o = 8; o > 0; o >>= 1)
        esum += __shfl_xor_sync(FULL, esum, o);

    if (sel) {
        float w = e / esum;
        int k = __popc(bal & ((1u << lane) - 1u));
        size_t NT = (size_t)N * topk;
        size_t base = (size_t)i * topk + k;
        out[base]          = (float)i;
        out[NT + base]     = (float)mycol;
        out[2 * NT + base] = w;
    }
}

// ---------------------------------------------------------------------------
extern "C" void kernel_launch(void* const* d_in, const int* in_sizes, int n_in,
                              void* d_out, int out_size)
{
    const float* x    = (const float*)d_in[0];
    const int*   eidx = (const int*)  d_in[1];
    const float* W    = (const float*)d_in[2];
    const float* logd = (const float*)d_in[3];
    const float* logt = (const float*)d_in[4];

    const int D   = 128;
    const int N   = in_sizes[0] / D;
    const int deg = in_sizes[1] / (2 * N);
    const int topk = out_size / (3 * N);

    float* out = (float*)d_out;

    const int smem_bytes = (128 + 4 * BUF_FLOATS) * sizeof(float);
    cudaFuncSetAttribute(proj_mma_kernel,
                         cudaFuncAttributeMaxDynamicSharedMemorySize, smem_bytes);
    proj_mma_kernel<<<(N + 127) / 128, 512, smem_bytes>>>(x, W, logd, N);

    int warps_per_block = 256 / 32;
    int blocks = (N + warps_per_block - 1) / warps_per_block;
    edge_kernel<<<blocks, 256>>>(eidx, logt, x, W, logd, out, N, deg, topk);
}

// round 10
// speedup vs baseline: 4.8552x; 4.8552x over previous
#include <cuda_runtime.h>
#include <math.h>
#include <math_constants.h>

#define D_DIM 128
#define MAXN  50048
#define EPS_F 1e-8f
#define FULL  0xffffffffu
#define GAP_THRESH 0.01f

typedef unsigned int u32;

__device__ float g_xp[(size_t)MAXN * D_DIM];

// ---------------------------------------------------------------------------
// tf32 helpers
// ---------------------------------------------------------------------------
__device__ __forceinline__ u32 to_tf32(float x) {
    u32 r; asm("cvt.rna.tf32.f32 %0, %1;" : "=r"(r) : "f"(x)); return r;
}
__device__ __forceinline__ void split_tf32(float x, u32& hi, u32& lo) {
    hi = to_tf32(x);
    float rem = x - __uint_as_float(hi);
    lo = to_tf32(rem);
}
__device__ __forceinline__ void mma_tf32(float* c, const u32* a, const u32* b) {
    asm volatile(
        "mma.sync.aligned.m16n8k8.row.col.f32.tf32.tf32.f32 "
        "{%0,%1,%2,%3}, {%4,%5,%6,%7}, {%8,%9}, {%0,%1,%2,%3};"
        : "+f"(c[0]), "+f"(c[1]), "+f"(c[2]), "+f"(c[3])
        : "r"(a[0]), "r"(a[1]), "r"(a[2]), "r"(a[3]), "r"(b[0]), "r"(b[1]));
}

#define KC    32
#define PITCH 36
#define BUF_FLOATS (128 * PITCH)

// ---------------------------------------------------------------------------
// Projection: Y = (X @ W^T) * sqrt(softplus(logd)+eps), 4-pass split-TF32.
// ---------------------------------------------------------------------------
__global__ __launch_bounds__(512, 1) void proj_mma_kernel(
    const float* __restrict__ X, const float* __restrict__ W,
    const float* __restrict__ logd, int N)
{
    extern __shared__ float smem[];
    float* scale = smem;
    float* Xhi = smem + 128;
    float* Xlo = Xhi + BUF_FLOATS;
    float* Whi = Xlo + BUF_FLOATS;
    float* Wlo = Whi + BUF_FLOATS;

    const int tid  = threadIdx.x;
    const int lane = tid & 31;
    const int wid  = tid >> 5;
    const int wm   = wid & 3;
    const int wn   = wid >> 2;
    const int m0   = blockIdx.x * 128;

    if (tid < 128) {
        float ld = logd[tid];
        float sp = (ld > 20.f) ? ld : log1pf(expf(ld));
        scale[tid] = sqrtf(sp + EPS_F);
    }

    float acc[2][4][4];
#pragma unroll
    for (int mt = 0; mt < 2; mt++)
#pragma unroll
        for (int nt = 0; nt < 4; nt++)
#pragma unroll
            for (int q = 0; q < 4; q++) acc[mt][nt][q] = 0.f;

    const int fr = lane >> 2;
    const int fc = lane & 3;

    for (int kt = 0; kt < 4; kt++) {
        __syncthreads();
#pragma unroll
        for (int it = 0; it < 2; it++) {
            int idx = tid + it * 512;
            int r   = idx >> 3;
            int k4  = (idx & 7) * 4;
            int gr = m0 + r;
            float4 xv = make_float4(0.f, 0.f, 0.f, 0.f);
            if (gr < N) xv = *(const float4*)(X + (size_t)gr * D_DIM + kt * KC + k4);
            u32 h0, l0, h1, l1, h2, l2, h3, l3;
            split_tf32(xv.x, h0, l0); split_tf32(xv.y, h1, l1);
            split_tf32(xv.z, h2, l2); split_tf32(xv.w, h3, l3);
            u32* xh = (u32*)(Xhi + r * PITCH + k4);
            u32* xl = (u32*)(Xlo + r * PITCH + k4);
            xh[0] = h0; xh[1] = h1; xh[2] = h2; xh[3] = h3;
            xl[0] = l0; xl[1] = l1; xl[2] = l2; xl[3] = l3;
            float4 wv = *(const float4*)(W + (size_t)r * D_DIM + kt * KC + k4);
            split_tf32(wv.x, h0, l0); split_tf32(wv.y, h1, l1);
            split_tf32(wv.z, h2, l2); split_tf32(wv.w, h3, l3);
            u32* wh = (u32*)(Whi + r * PITCH + k4);
            u32* wl = (u32*)(Wlo + r * PITCH + k4);
            wh[0] = h0; wh[1] = h1; wh[2] = h2; wh[3] = h3;
            wl[0] = l0; wl[1] = l1; wl[2] = l2; wl[3] = l3;
        }
        __syncthreads();

#pragma unroll
        for (int ks = 0; ks < KC / 8; ks++) {
            u32 ah[2][4], al[2][4];
#pragma unroll
            for (int mt = 0; mt < 2; mt++) {
                int rb = (wm * 32 + mt * 16 + fr) * PITCH + ks * 8 + fc;
                ah[mt][0] = *(u32*)(Xhi + rb);
                ah[mt][1] = *(u32*)(Xhi + rb + 8 * PITCH);
                ah[mt][2] = *(u32*)(Xhi + rb + 4);
                ah[mt][3] = *(u32*)(Xhi + rb + 8 * PITCH + 4);
                al[mt][0] = *(u32*)(Xlo + rb);
                al[mt][1] = *(u32*)(Xlo + rb + 8 * PITCH);
                al[mt][2] = *(u32*)(Xlo + rb + 4);
                al[mt][3] = *(u32*)(Xlo + rb + 8 * PITCH + 4);
            }
            u32 bh[4][2], bl[4][2];
#pragma unroll
            for (int nt = 0; nt < 4; nt++) {
                int nb = (wn * 32 + nt * 8 + fr) * PITCH + ks * 8 + fc;
                bh[nt][0] = *(u32*)(Whi + nb);
                bh[nt][1] = *(u32*)(Whi + nb + 4);
                bl[nt][0] = *(u32*)(Wlo + nb);
                bl[nt][1] = *(u32*)(Wlo + nb + 4);
            }
#pragma unroll
            for (int mt = 0; mt < 2; mt++)
#pragma unroll
                for (int nt = 0; nt < 4; nt++) {
                    mma_tf32(acc[mt][nt], ah[mt], bh[nt]);
                    mma_tf32(acc[mt][nt], ah[mt], bl[nt]);
                    mma_tf32(acc[mt][nt], al[mt], bh[nt]);
                    mma_tf32(acc[mt][nt], al[mt], bl[nt]);
                }
        }
    }

#pragma unroll
    for (int mt = 0; mt < 2; mt++) {
        int row0 = m0 + wm * 32 + mt * 16 + fr;
#pragma unroll
        for (int nt = 0; nt < 4; nt++) {
            int col = wn * 32 + nt * 8 + 2 * fc;
            float s0 = scale[col], s1 = scale[col + 1];
            if (row0 < N) {
                float2 o0 = make_float2(acc[mt][nt][0] * s0, acc[mt][nt][1] * s1);
                *(float2*)(g_xp + (size_t)row0 * D_DIM + col) = o0;
            }
            if (row0 + 8 < N) {
                float2 o1 = make_float2(acc[mt][nt][2] * s0, acc[mt][nt][3] * s1);
                *(float2*)(g_xp + (size_t)(row0 + 8) * D_DIM + col) = o1;
            }
        }
    }
}

// ---------------------------------------------------------------------------
// Exact y-row recompute, FAST version: float4 loads, unrolled so loads
// pipeline; the four fmaf chains keep ascending-k sequential order (bitwise
// identical realization to the fp32-sequential proj that passes).
// Lane holds dims [4*lane, 4*lane+4).
// ---------------------------------------------------------------------------
__device__ __noinline__ float4 exact_row(
    const float* __restrict__ X, const float* __restrict__ W,
    const float* __restrict__ logd, int r, int lane)
{
    const float4* xr = (const float4*)(X + (size_t)r * D_DIM);
    const float4* w0 = (const float4*)(W + (size_t)(4 * lane + 0) * D_DIM);
    const float4* w1 = (const float4*)(W + (size_t)(4 * lane + 1) * D_DIM);
    const float4* w2 = (const float4*)(W + (size_t)(4 * lane + 2) * D_DIM);
    const float4* w3 = (const float4*)(W + (size_t)(4 * lane + 3) * D_DIM);
    float a0 = 0.f, a1 = 0.f, a2 = 0.f, a3 = 0.f;
#pragma unroll
    for (int k4 = 0; k4 < D_DIM / 4; k4++) {
        float4 xv = xr[k4];
        float4 v0 = w0[k4], v1 = w1[k4], v2 = w2[k4], v3 = w3[k4];
        a0 = fmaf(xv.x, v0.x, a0); a0 = fmaf(xv.y, v0.y, a0);
        a0 = fmaf(xv.z, v0.z, a0); a0 = fmaf(xv.w, v0.w, a0);
        a1 = fmaf(xv.x, v1.x, a1); a1 = fmaf(xv.y, v1.y, a1);
        a1 = fmaf(xv.z, v1.z, a1); a1 = fmaf(xv.w, v1.w, a1);
        a2 = fmaf(xv.x, v2.x, a2); a2 = fmaf(xv.y, v2.y, a2);
        a2 = fmaf(xv.z, v2.z, a2); a2 = fmaf(xv.w, v2.w, a2);
        a3 = fmaf(xv.x, v3.x, a3); a3 = fmaf(xv.y, v3.y, a3);
        a3 = fmaf(xv.z, v3.z, a3); a3 = fmaf(xv.w, v3.w, a3);
    }
    float4 ld4 = *(const float4*)(logd + 4 * lane);
    float4 y;
    { float sp = (ld4.x > 20.f) ? ld4.x : log1pf(expf(ld4.x)); y.x = a0 * sqrtf(sp + EPS_F); }
    { float sp = (ld4.y > 20.f) ? ld4.y : log1pf(expf(ld4.y)); y.y = a1 * sqrtf(sp + EPS_F); }
    { float sp = (ld4.z > 20.f) ? ld4.z : log1pf(expf(ld4.z)); y.z = a2 * sqrtf(sp + EPS_F); }
    { float sp = (ld4.w > 20.f) ? ld4.w : log1pf(expf(ld4.w)); y.w = a3 * sqrtf(sp + EPS_F); }
    return y;
}

// Butterfly transpose-reduce: p[16] per-lane partials -> lane n holds
// neighbor n's full 128-dim sum.
__device__ __forceinline__ float butterfly_score(float* p, int lane) {
    const bool b0 = lane & 1;
#pragma unroll
    for (int k = 0; k < 8; k++) {
        float send = b0 ? p[k] : p[k + 8];
        float recv = __shfl_xor_sync(FULL, send, 1);
        p[k] = (b0 ? p[k + 8] : p[k]) + recv;
    }
    const bool b1 = lane & 2;
#pragma unroll
    for (int k = 0; k < 4; k++) {
        float send = b1 ? p[k] : p[k + 4];
        float recv = __shfl_xor_sync(FULL, send, 2);
        p[k] = (b1 ? p[k + 4] : p[k]) + recv;
    }
    const bool b2 = lane & 4;
#pragma unroll
    for (int k = 0; k < 2; k++) {
        float send = b2 ? p[k] : p[k + 2];
        float recv = __shfl_xor_sync(FULL, send, 4);
        p[k] = (b2 ? p[k + 2] : p[k]) + recv;
    }
    const bool b3 = lane & 8;
    {
        float send = b3 ? p[0] : p[1];
        float recv = __shfl_xor_sync(FULL, send, 8);
        p[0] = (b3 ? p[1] : p[0]) + recv;
    }
    p[0] += __shfl_xor_sync(FULL, p[0], 16);
    const int l4  = lane & 15;
    const int rev = ((l4 & 1) << 3) | ((l4 & 2) << 1) | ((l4 & 4) >> 1) | ((l4 & 8) >> 3);
    return __shfl_sync(FULL, p[0], rev);
}

__device__ __forceinline__ void diff_sq(const float4& yi, const float4& v, float& out) {
    float dx = yi.x - v.x, dy = yi.y - v.y;
    float dz = yi.z - v.z, dw = yi.w - v.w;
    out = dx * dx + dy * dy + dz * dz + dw * dw;
}

// ---------------------------------------------------------------------------
// Edge kernel: MMA-y scores; small-margin nodes repaired exactly.
// ---------------------------------------------------------------------------
__global__ __launch_bounds__(256, 5) void edge_kernel(
    const int* __restrict__ eidx, const float* __restrict__ logt,
    const float* __restrict__ X, const float* __restrict__ W,
    const float* __restrict__ logd,
    float* __restrict__ out, int N, int deg, int topk)
{
    const int warp = blockIdx.x * (blockDim.x >> 5) + (threadIdx.x >> 5);
    const int lane = threadIdx.x & 31;
    if (warp >= N) return;
    const int i = warp;

    const int* colp = eidx + (size_t)N * deg + (size_t)i * deg;
    int mycol = (lane < 16) ? colp[lane] : 0;

    const float rtemp = expf(-logt[0]);

    float s;
    {
        float4 yi = *(const float4*)(g_xp + (size_t)i * D_DIM + lane * 4);
        float p[16];
#pragma unroll
        for (int g = 0; g < 4; g++) {
            float4 v[4];
#pragma unroll
            for (int n = 0; n < 4; n++) {
                int c = __shfl_sync(FULL, mycol, g * 4 + n);
                v[n] = *(const float4*)(g_xp + (size_t)c * D_DIM + lane * 4);
            }
#pragma unroll
            for (int n = 0; n < 4; n++) diff_sq(yi, v[n], p[g * 4 + n]);
        }
        float raw = butterfly_score(p, lane);
        s = (lane < 16) ? (-raw * rtemp) : -CUDART_INF_F;
    }

    int rank = 0;
#pragma unroll
    for (int m = 0; m < 16; m++) {
        float sm = __shfl_sync(FULL, s, m);
        rank += (sm > s || (sm == s && m < lane)) ? 1 : 0;
    }
    bool sel = rank < topk;

    // selection margin: min(selected) - max(unselected)
    {
        float m1 = sel ? s : CUDART_INF_F;
        float m2 = (!sel && lane < 16) ? s : -CUDART_INF_F;
#pragma unroll
        for (int o = 16; o > 0; o >>= 1) {
            m1 = fminf(m1, __shfl_xor_sync(FULL, m1, o));
            m2 = fmaxf(m2, __shfl_xor_sync(FULL, m2, o));
        }
        if (m1 - m2 < GAP_THRESH) {
            float4 yi = exact_row(X, W, logd, i, lane);
            float p[16];
#pragma unroll 1
            for (int n = 0; n < 16; n++) {
                int c = __shfl_sync(FULL, mycol, n);
                float4 v = exact_row(X, W, logd, c, lane);
                diff_sq(yi, v, p[n]);
            }
            float raw = butterfly_score(p, lane);
            s = (lane < 16) ? (-raw * rtemp) : -CUDART_INF_F;
            rank = 0;
#pragma unroll
            for (int m = 0; m < 16; m++) {
                float sm = __shfl_sync(FULL, s, m);
                rank += (sm > s || (sm == s && m < lane)) ? 1 : 0;
            }
            sel = rank < topk;
        }
    }

    unsigned bal = __ballot_sync(FULL, sel);

    float smax = sel ? s : -CUDART_INF_F;
#pragma unroll
    for (int o = 8; o > 0; o >>= 1)
        smax = fmaxf(smax, __shfl_xor_sync(FULL, smax, o));
    float e = sel ? expf(s - smax) : 0.f;
    float esum = e;
#pragma unroll
    for (int o = 8; o > 0; o >>= 1)
        esum += __shfl_xor_sync(FULL, esum, o);

    if (sel) {
        float w = e / esum;
        int k = __popc(bal & ((1u << lane) - 1u));
        size_t NT = (size_t)N * topk;
        size_t base = (size_t)i * topk + k;
        out[base]          = (float)i;
        out[NT + base]     = (float)mycol;
        out[2 * NT + base] = w;
    }
}

// ---------------------------------------------------------------------------
extern "C" void kernel_launch(void* const* d_in, const int* in_sizes, int n_in,
                              void* d_out, int out_size)
{
    const float* x    = (const float*)d_in[0];
    const int*   eidx = (const int*)  d_in[1];
    const float* W    = (const float*)d_in[2];
    const float* logd = (const float*)d_in[3];
    const float* logt = (const float*)d_in[4];

    const int D   = 128;
    const int N   = in_sizes[0] / D;
    const int deg = in_sizes[1] / (2 * N);
    const int topk = out_size / (3 * N);

    float* out = (float*)d_out;

    const int smem_bytes = (128 + 4 * BUF_FLOATS) * sizeof(float);
    cudaFuncSetAttribute(proj_mma_kernel,
                         cudaFuncAttributeMaxDynamicSharedMemorySize, smem_bytes);
    proj_mma_kernel<<<(N + 127) / 128, 512, smem_bytes>>>(x, W, logd, N);

    int warps_per_block = 256 / 32;
    int blocks = (N + warps_per_block - 1) / warps_per_block;
    edge_kernel<<<blocks, 256>>>(eidx, logt, x, W, logd, out, N, deg, topk);
}